// round 1
// baseline (speedup 1.0000x reference)
#include <cuda_runtime.h>
#include <math.h>

#define C_    256
#define NLAT_ 256
#define NLON_ 512
#define L_    256
#define M_    257
#define NREF_ 64
#define S_    (NLAT_*NLON_)          // 131072 = 2^17
#define LMJ_  (L_*M_*NLAT_)          // 16,842,752

// ---------------- device scratch (static globals; no allocs) ----------------
__device__ float g_Dc [M_*NLON_];
__device__ float g_Ds [M_*NLON_];
__device__ float g_Dc2[NLON_*M_];
__device__ float g_Ds2[NLON_*M_];
__device__ float g_lw  [LMJ_];              // (L, M, NLAT) legfuncs*wquad
__device__ float g_legT[M_*NLAT_*L_];       // (M, NLAT, L)
__device__ float g_Wre [L_*C_*C_];          // (L, F, C)
__device__ float g_Wim [L_*C_*C_];
__device__ float g_Fre [M_*C_*NLAT_];       // (M, C, NLAT)
__device__ float g_Fim [M_*C_*NLAT_];
__device__ float g_hre [M_*L_*C_];          // (M, L, C)
__device__ float g_him [M_*L_*C_];
__device__ float g_xre [C_*M_*L_];          // (F, M, L)
__device__ float g_xim [C_*M_*L_];
__device__ float g_Gre [C_*NLAT_*M_];       // (F, NLAT, M)
__device__ float g_Gim [C_*NLAT_*M_];
__device__ float g_grids[(long)C_*S_];      // (F, NLAT, NLON) -> later y2
__device__ float g_mlp1 [(long)C_*S_];      // h1 -> h2
__device__ float g_mlp2 [(long)C_*S_];      // added
__device__ float g_wT[4][C_*C_];
__device__ float g_lscale[L_];
__device__ float g_mu[C_];
__device__ float g_rstd[C_];

// ---------------- helpers ----------------
__device__ __forceinline__ float gelu_f(float v){
    return 0.5f*v*(1.0f + erff(v*0.7071067811865476f));
}

// ---------------- prep kernels ----------------
__global__ void prep_tables_k(){
    int idx = blockIdx.x*blockDim.x + threadIdx.x;
    if (idx >= M_*NLON_) return;
    int m = idx / NLON_, n = idx % NLON_;
    int a = (m*n) & (NLON_-1);
    float ang = (float)a * (1.0f/256.0f);   // in units of pi
    float c = cospif(ang);
    float s = sinpif(ang);
    g_Dc[m*NLON_+n] = c;
    g_Ds[m*NLON_+n] = -s;                   // Im part of rfft = -sum x*sin
    float wm = (m==0 || m==M_-1) ? 1.0f : 2.0f;
    g_Dc2[n*M_+m] =  wm*c*(1.0f/NLON_);
    g_Ds2[n*M_+m] = -wm*s*(1.0f/NLON_);     // irfft: (Re*cos - Im*sin)/N
}

__global__ void prep_lw_k(const float* __restrict__ leg, const float* __restrict__ wq){
    int idx = blockIdx.x*blockDim.x + threadIdx.x;
    if (idx >= LMJ_) return;
    g_lw[idx] = leg[idx] * wq[idx & (NLAT_-1)];
}

__global__ void prep_legT_k(const float* __restrict__ leg){
    int idx = blockIdx.x*blockDim.x + threadIdx.x;
    if (idx >= M_*NLAT_*L_) return;
    int l = idx % L_;
    int j = (idx / L_) % NLAT_;
    int m = idx / (L_*NLAT_);
    g_legT[idx] = leg[(long)l*M_*NLAT_ + (long)m*NLAT_ + j];
}

__global__ void prep_W_k(const float* __restrict__ wr, const float* __restrict__ wi){
    int idx = blockIdx.x*blockDim.x + threadIdx.x;
    if (idx >= L_*C_*C_) return;
    int c = idx % C_;
    int f = (idx / C_) % C_;
    int l = idx / (C_*C_);
    float pos = (float)(l*(NREF_-1)) / (float)(L_-1);
    int i0 = (int)floorf(pos);
    if (i0 < 0) i0 = 0;
    if (i0 > NREF_-2) i0 = NREF_-2;
    float fr = pos - (float)i0;
    long base = ((long)f*C_ + c)*NREF_ + i0;
    g_Wre[idx] = wr[base]*(1.0f-fr) + wr[base+1]*fr;
    g_Wim[idx] = wi[base]*(1.0f-fr) + wi[base+1]*fr;
}

__global__ void prep_misc_k(const float* w1, const float* w2,
                            const float* w3, const float* w4){
    int idx = blockIdx.x*blockDim.x + threadIdx.x;
    if (idx < L_) g_lscale[idx] = sqrtf(1.0f + (float)idx) * (1.0f/(float)C_);
    if (idx >= C_*C_) return;
    int c = idx / C_, cp = idx % C_;
    g_wT[0][cp*C_+c] = w1[c*C_+cp];
    g_wT[1][cp*C_+c] = w2[c*C_+cp];
    g_wT[2][cp*C_+c] = w3[c*C_+cp];
    g_wT[3][cp*C_+c] = w4[c*C_+cp];
}

// ---------------- flexible-stride (dual-MAC) tiled SGEMM ----------------
// C[b,i,j] = scale(b) * ( sum_k A1[b,i,k]*B1[b,*,k or k,*] (+ sign2 * A2*B2) )
//            (+ bias[i]) -> ACT -> (+ addsrc[same strides as C])
// A is always k-contiguous. If BK1: B is k-contiguous (stride sB1 over j),
// else B is j-contiguous (stride sB1 over k).
template<bool BK1, bool DUAL, int ACT>
__global__ __launch_bounds__(256) void gemm_k(
    const float* __restrict__ A1, const float* __restrict__ B1,
    const float* __restrict__ A2, const float* __restrict__ B2,
    float sign2,
    float* __restrict__ Cout,
    const float* __restrict__ bias,
    const float* __restrict__ bscale,
    const float* __restrict__ addsrc,
    int M, int N, int K,
    int sAi, int sAb,
    int sB1, int sBb,
    long sCi, int sCj, long sCb)
{
    __shared__ float As1[32][65];
    __shared__ float Bs1[32][65];
    __shared__ float As2[DUAL?32:1][DUAL?65:1];
    __shared__ float Bs2[DUAL?32:1][DUAL?65:1];

    int t  = threadIdx.x;
    int bz = blockIdx.z;
    long i0 = (long)blockIdx.y * 64;
    long j0 = (long)blockIdx.x * 64;

    const float* A1b = A1 + (long)bz*sAb;
    const float* B1b = B1 + (long)bz*sBb;
    const float* A2b = DUAL ? (A2 + (long)bz*sAb) : A1;
    const float* B2b = DUAL ? (B2 + (long)bz*sBb) : B1;

    float acc1[4][4];
    float acc2[4][4];
    #pragma unroll
    for (int r=0;r<4;r++)
        #pragma unroll
        for (int s=0;s<4;s++){ acc1[r][s]=0.f; if (DUAL) acc2[r][s]=0.f; }

    int ib = (t>>4)*4, jb = (t&15)*4;

    for (int k0=0; k0<K; k0+=32){
        {   // load A tile: k fast (contiguous)
            int kk = t & 31, irow0 = t >> 5;
            int kg = k0 + kk; bool kok = (kg < K);
            #pragma unroll
            for (int r=0;r<8;r++){
                int ii = irow0 + r*8;
                long ig = i0 + ii;
                bool ok = kok && (ig < (long)M);
                As1[kk][ii] = ok ? A1b[ig*(long)sAi + kg] : 0.f;
                if (DUAL) As2[kk][ii] = ok ? A2b[ig*(long)sAi + kg] : 0.f;
            }
        }
        if (BK1){
            int kk = t & 31, jrow0 = t >> 5;
            int kg = k0 + kk; bool kok = (kg < K);
            #pragma unroll
            for (int r=0;r<8;r++){
                int jj = jrow0 + r*8;
                long jg = j0 + jj;
                bool ok = kok && (jg < (long)N);
                Bs1[kk][jj] = ok ? B1b[jg*(long)sB1 + kg] : 0.f;
                if (DUAL) Bs2[kk][jj] = ok ? B2b[jg*(long)sB1 + kg] : 0.f;
            }
        } else {
            int jj = t & 63, krow0 = t >> 6;
            long jg = j0 + jj; bool jok = (jg < (long)N);
            #pragma unroll
            for (int r=0;r<8;r++){
                int kk = krow0 + r*4;
                int kg = k0 + kk;
                bool ok = jok && (kg < K);
                Bs1[kk][jj] = ok ? B1b[(long)kg*sB1 + jg] : 0.f;
                if (DUAL) Bs2[kk][jj] = ok ? B2b[(long)kg*sB1 + jg] : 0.f;
            }
        }
        __syncthreads();
        #pragma unroll
        for (int kk=0; kk<32; kk++){
            float a1[4], b1[4], a2[4], b2[4];
            #pragma unroll
            for (int r=0;r<4;r++){ a1[r]=As1[kk][ib+r]; if (DUAL) a2[r]=As2[kk][ib+r]; }
            #pragma unroll
            for (int s=0;s<4;s++){ b1[s]=Bs1[kk][jb+s]; if (DUAL) b2[s]=Bs2[kk][jb+s]; }
            #pragma unroll
            for (int r=0;r<4;r++)
                #pragma unroll
                for (int s=0;s<4;s++){
                    acc1[r][s] = fmaf(a1[r], b1[s], acc1[r][s]);
                    if (DUAL) acc2[r][s] = fmaf(a2[r], b2[s], acc2[r][s]);
                }
        }
        __syncthreads();
    }

    float scl = bscale ? bscale[bz] : 1.0f;
    #pragma unroll
    for (int r=0;r<4;r++){
        long ig = i0 + ib + r;
        if (ig >= (long)M) continue;
        #pragma unroll
        for (int s=0;s<4;s++){
            long jg = j0 + jb + s;
            if (jg >= (long)N) continue;
            float v = acc1[r][s];
            if (DUAL) v += sign2*acc2[r][s];
            v *= scl;
            if (bias) v += bias[ig];
            if (ACT==1) v = gelu_f(v);
            long off = (long)bz*sCb + ig*sCi + jg*(long)sCj;
            if (addsrc) v += addsrc[off];
            Cout[off] = v;
        }
    }
}

// ---------------- norm + residual ----------------
__global__ void norm_reduce_k(){
    int c = blockIdx.x, t = threadIdx.x;
    const float* row = g_grids + (long)c*S_;
    float s=0.f, s2=0.f;
    for (int i=t; i<S_; i+=256){ float v=row[i]; s+=v; s2=fmaf(v,v,s2); }
    __shared__ float sh[256], sh2[256];
    sh[t]=s; sh2[t]=s2; __syncthreads();
    for (int o=128;o>0;o>>=1){
        if (t<o){ sh[t]+=sh[t+o]; sh2[t]+=sh2[t+o]; }
        __syncthreads();
    }
    if (t==0){
        float m   = sh[0]*(1.0f/(float)S_);
        float var = sh2[0]*(1.0f/(float)S_) - m*m;
        g_mu[c]   = m;
        g_rstd[c] = rsqrtf(var + 1e-3f);
    }
}

__global__ void finalize_k(const float* __restrict__ x,
                           const float* __restrict__ gamma,
                           const float* __restrict__ beta,
                           float* __restrict__ out){
    long idx = (long)blockIdx.x*256 + threadIdx.x;
    if (idx >= (long)C_*S_) return;
    int c = (int)(idx >> 17);   // S_ = 2^17
    out[idx] = (g_grids[idx]-g_mu[c])*g_rstd[c]*gamma[c] + beta[c] + x[idx];
}

// ---------------- launch ----------------
static inline dim3 gdim(int N, int M, int b){
    return dim3((unsigned)((N+63)/64), (unsigned)((M+63)/64), (unsigned)b);
}

extern "C" void kernel_launch(void* const* d_in, const int* in_sizes, int n_in,
                              void* d_out, int out_size){
    const float* x      = (const float*)d_in[0];
    const float* leg    = (const float*)d_in[1];
    const float* wquad  = (const float*)d_in[2];
    const float* w_real = (const float*)d_in[3];
    const float* w_imag = (const float*)d_in[4];
    const float* m1w1   = (const float*)d_in[5];
    const float* m1b1   = (const float*)d_in[6];
    const float* m1w2   = (const float*)d_in[7];
    const float* m1b2   = (const float*)d_in[8];
    const float* m2w1   = (const float*)d_in[9];
    const float* m2b1   = (const float*)d_in[10];
    const float* m2w2   = (const float*)d_in[11];
    const float* m2b2   = (const float*)d_in[12];
    const float* gamma  = (const float*)d_in[13];
    const float* beta   = (const float*)d_in[14];
    float* out = (float*)d_out;

    float *Dc,*Ds,*Dc2,*Ds2,*lw,*legT,*Wre,*Wim,*Fre,*Fim,*hre,*him,
          *xre,*xim,*Gre,*Gim,*grids,*mlp1,*mlp2,*wT,*lsc;
    cudaGetSymbolAddress((void**)&Dc,  g_Dc);
    cudaGetSymbolAddress((void**)&Ds,  g_Ds);
    cudaGetSymbolAddress((void**)&Dc2, g_Dc2);
    cudaGetSymbolAddress((void**)&Ds2, g_Ds2);
    cudaGetSymbolAddress((void**)&lw,  g_lw);
    cudaGetSymbolAddress((void**)&legT,g_legT);
    cudaGetSymbolAddress((void**)&Wre, g_Wre);
    cudaGetSymbolAddress((void**)&Wim, g_Wim);
    cudaGetSymbolAddress((void**)&Fre, g_Fre);
    cudaGetSymbolAddress((void**)&Fim, g_Fim);
    cudaGetSymbolAddress((void**)&hre, g_hre);
    cudaGetSymbolAddress((void**)&him, g_him);
    cudaGetSymbolAddress((void**)&xre, g_xre);
    cudaGetSymbolAddress((void**)&xim, g_xim);
    cudaGetSymbolAddress((void**)&Gre, g_Gre);
    cudaGetSymbolAddress((void**)&Gim, g_Gim);
    cudaGetSymbolAddress((void**)&grids, g_grids);
    cudaGetSymbolAddress((void**)&mlp1,  g_mlp1);
    cudaGetSymbolAddress((void**)&mlp2,  g_mlp2);
    cudaGetSymbolAddress((void**)&wT,    g_wT);
    cudaGetSymbolAddress((void**)&lsc,   g_lscale);

    // ---- prep ----
    prep_tables_k<<<(M_*NLON_+255)/256, 256>>>();
    prep_lw_k    <<<(LMJ_+255)/256, 256>>>(leg, wquad);
    prep_legT_k  <<<(M_*NLAT_*L_+255)/256, 256>>>(leg);
    prep_W_k     <<<(L_*C_*C_+255)/256, 256>>>(w_real, w_imag);
    prep_misc_k  <<<(C_*C_+255)/256, 256>>>(m1w1, m1w2, m2w1, m2w2);

    // ---- S1: rfft as DFT GEMM. out (M, C*NLAT) ----
    gemm_k<true,false,0><<<gdim(C_*NLAT_, M_, 1), 256>>>(
        Dc, x, nullptr, nullptr, 0.f, Fre, nullptr, nullptr, nullptr,
        M_, C_*NLAT_, NLON_, NLON_, 0, NLON_, 0, (long)(C_*NLAT_), 1, 0);
    gemm_k<true,false,0><<<gdim(C_*NLAT_, M_, 1), 256>>>(
        Ds, x, nullptr, nullptr, 0.f, Fim, nullptr, nullptr, nullptr,
        M_, C_*NLAT_, NLON_, NLON_, 0, NLON_, 0, (long)(C_*NLAT_), 1, 0);

    // ---- S2: harms[m][l][c] = sum_j lw[l,m,j] F[m,c,j]  (batch m) ----
    gemm_k<true,false,0><<<gdim(C_, L_, M_), 256>>>(
        lw, Fre, nullptr, nullptr, 0.f, hre, nullptr, nullptr, nullptr,
        L_, C_, NLAT_, M_*NLAT_, NLAT_, NLAT_, C_*NLAT_, (long)C_, 1, (long)(L_*C_));
    gemm_k<true,false,0><<<gdim(C_, L_, M_), 256>>>(
        lw, Fim, nullptr, nullptr, 0.f, him, nullptr, nullptr, nullptr,
        L_, C_, NLAT_, M_*NLAT_, NLAT_, NLAT_, C_*NLAT_, (long)C_, 1, (long)(L_*C_));

    // ---- S3: xs[f][m][l] = lfac(l)/C * sum_c W[l,f,c]*harms[m,l,c]  (complex, batch l) ----
    gemm_k<true,true,0><<<gdim(M_, C_, L_), 256>>>(
        Wre, hre, Wim, him, -1.f, xre, nullptr, lsc, nullptr,
        C_, M_, C_, C_, C_*C_, L_*C_, C_, (long)(M_*L_), L_, 1);
    gemm_k<true,true,0><<<gdim(M_, C_, L_), 256>>>(
        Wre, him, Wim, hre, +1.f, xim, nullptr, lsc, nullptr,
        C_, M_, C_, C_, C_*C_, L_*C_, C_, (long)(M_*L_), L_, 1);

    // ---- S4: G[f][j][m] = sum_l legT[m,j,l]*xs[f,m,l]  (batch m) ----
    gemm_k<true,false,0><<<gdim(NLAT_, C_, M_), 256>>>(
        xre, legT, nullptr, nullptr, 0.f, Gre, nullptr, nullptr, nullptr,
        C_, NLAT_, L_, M_*L_, L_, L_, NLAT_*L_, (long)(NLAT_*M_), M_, 1);
    gemm_k<true,false,0><<<gdim(NLAT_, C_, M_), 256>>>(
        xim, legT, nullptr, nullptr, 0.f, Gim, nullptr, nullptr, nullptr,
        C_, NLAT_, L_, M_*L_, L_, L_, NLAT_*L_, (long)(NLAT_*M_), M_, 1);

    // ---- S5: irfft as dual GEMM + GELU. grids (F*NLAT, NLON) ----
    gemm_k<true,true,1><<<gdim(NLON_, C_*NLAT_, 1), 256>>>(
        Gre, Dc2, Gim, Ds2, +1.f, grids, nullptr, nullptr, nullptr,
        C_*NLAT_, NLON_, M_, M_, 0, M_, 0, (long)NLON_, 1, 0);

    // ---- MLPs: (C',S) = gelu(W^T @ X + b) [+ add] ----
    gemm_k<false,false,1><<<gdim(S_, C_, 1), 256>>>(
        wT + 0*C_*C_, x, nullptr, nullptr, 0.f, mlp1, m1b1, nullptr, nullptr,
        C_, S_, C_, C_, 0, S_, 0, (long)S_, 1, 0);
    gemm_k<false,false,1><<<gdim(S_, C_, 1), 256>>>(
        wT + 1*C_*C_, mlp1, nullptr, nullptr, 0.f, mlp2, m1b2, nullptr, grids,
        C_, S_, C_, C_, 0, S_, 0, (long)S_, 1, 0);
    gemm_k<false,false,1><<<gdim(S_, C_, 1), 256>>>(
        wT + 2*C_*C_, mlp2, nullptr, nullptr, 0.f, mlp1, m2b1, nullptr, nullptr,
        C_, S_, C_, C_, 0, S_, 0, (long)S_, 1, 0);
    gemm_k<false,false,1><<<gdim(S_, C_, 1), 256>>>(
        wT + 3*C_*C_, mlp1, nullptr, nullptr, 0.f, grids, m2b2, nullptr, nullptr,
        C_, S_, C_, C_, 0, S_, 0, (long)S_, 1, 0);

    // ---- instance norm + residual ----
    norm_reduce_k<<<C_, 256>>>();
    finalize_k<<<(unsigned)(((long)C_*S_+255)/256), 256>>>(x, gamma, beta, out);
}

// round 2
// speedup vs baseline: 1.9136x; 1.9136x over previous
#include <cuda_runtime.h>
#include <cuda_bf16.h>
#include <math.h>

#define C_    256
#define NLAT_ 256
#define NLON_ 512
#define L_    256
#define M_    257
#define NREF_ 64
#define S_    (NLAT_*NLON_)      // 131072
#define K2C_  512                // 2*C for complex concat
#define MP_   528                // 2*M=514 padded to mult of 16

// sizes
#define XS_SZ   ((size_t)C_*S_)                  // 33554432
#define LW_SZ   ((size_t)L_*M_*NLAT_)            // 16842752
#define LGT_SZ  ((size_t)M_*NLAT_*L_)            // 16842752
#define WC_SZ   ((size_t)L_*C_*K2C_)             // 33554432
#define F_SZ    ((size_t)2*M_*C_*NLAT_)          // 33685504
#define H_SZ    ((size_t)L_*M_*K2C_)             // 33685504
#define XSP_SZ  ((size_t)M_*C_*L_)               // 16842752
#define G2_SZ   ((size_t)NLAT_*C_*MP_)           // 34603008
#define DCS_SZ  ((size_t)2*M_*NLON_)             // 263168
#define D2_SZ   ((size_t)NLON_*MP_)              // 270336

// ---------------- device scratch (split bf16 pairs + fp32) ----------------
__device__ __align__(128) __nv_bfloat16 g_x_h[XS_SZ],  g_x_l[XS_SZ];    // (c,j,n)
__device__ __align__(128) __nv_bfloat16 g_xt_h[XS_SZ], g_xt_l[XS_SZ];   // (s,c)
__device__ __align__(128) __nv_bfloat16 g_lw_h[LW_SZ], g_lw_l[LW_SZ];   // (l,m,j)
__device__ __align__(128) __nv_bfloat16 g_lg_h[LGT_SZ],g_lg_l[LGT_SZ];  // (m,j,l)
__device__ __align__(128) __nv_bfloat16 g_wr_h[WC_SZ], g_wr_l[WC_SZ];   // [Wre|-Wim] (l,f,2C)
__device__ __align__(128) __nv_bfloat16 g_wi_h[WC_SZ], g_wi_l[WC_SZ];   // [Wim| Wre]
__device__ __align__(128) __nv_bfloat16 g_F_h[F_SZ],   g_F_l[F_SZ];     // (ri,m,c,j)
__device__ __align__(128) __nv_bfloat16 g_H_h[H_SZ],   g_H_l[H_SZ];     // (l,m,2C)
__device__ __align__(128) __nv_bfloat16 g_xr_h[XSP_SZ],g_xr_l[XSP_SZ];  // (m,f,l) re
__device__ __align__(128) __nv_bfloat16 g_xi_h[XSP_SZ],g_xi_l[XSP_SZ];  // (m,f,l) im
__device__ __align__(128) __nv_bfloat16 g_G_h[G2_SZ],  g_G_l[G2_SZ];    // (j,f,528)
__device__ __align__(128) __nv_bfloat16 g_mA_h[XS_SZ], g_mA_l[XS_SZ];   // mlp scratch (s,c)
__device__ __align__(128) __nv_bfloat16 g_mB_h[XS_SZ], g_mB_l[XS_SZ];
__device__ __align__(128) __nv_bfloat16 g_dc_h[DCS_SZ],g_dc_l[DCS_SZ];  // (ri,m,n)
__device__ __align__(128) __nv_bfloat16 g_d2_h[D2_SZ], g_d2_l[D2_SZ];   // (n,528)
__device__ __align__(128) __nv_bfloat16 g_wt_h[4*C_*C_], g_wt_l[4*C_*C_]; // wT (c',c)
__device__ __align__(128) float g_grids[XS_SZ];                          // (n,j,f) then y2 (s,c)
__device__ float g_lsc[L_];
__device__ float g_part[2][512][C_];
__device__ float g_mu[C_], g_rstd[C_];

// ---------------- helpers ----------------
__device__ __forceinline__ float gelu_f(float v){
    return 0.5f*v*(1.0f + erff(v*0.7071067811865476f));
}
__device__ __forceinline__ void split2(float v, __nv_bfloat16* H, __nv_bfloat16* Lo, size_t off){
    __nv_bfloat16 h = __float2bfloat16(v);
    H[off]  = h;
    Lo[off] = __float2bfloat16(v - __bfloat162float(h));
}

// ---------------- prep kernels ----------------
__global__ void p_split_x(const float* __restrict__ x){
    size_t i = (size_t)blockIdx.x*256 + threadIdx.x;
    if (i >= XS_SZ) return;
    split2(x[i], g_x_h, g_x_l, i);
}

// x (c,j,n) -> xT (s=n*256+j, c), tiled transpose
__global__ void p_xT(const float* __restrict__ x){
    __shared__ float sm[32][33];
    int j  = blockIdx.y;
    int tc = blockIdx.x & 7;          // c tile (8)
    int tn = blockIdx.x >> 3;         // n tile (16)
    int tx = threadIdx.x, ty = threadIdx.y;
    #pragma unroll
    for (int k=0;k<4;k++){
        int c = tc*32 + ty + k*8;
        sm[ty+k*8][tx] = x[(size_t)c*S_ + (size_t)j*NLON_ + tn*32 + tx];
    }
    __syncthreads();
    #pragma unroll
    for (int k=0;k<4;k++){
        int n = tn*32 + ty + k*8;
        int c = tc*32 + tx;
        size_t off = ((size_t)n*NLAT_ + j)*C_ + c;
        split2(sm[tx][ty+k*8], g_xt_h, g_xt_l, off);
    }
}

__global__ void p_lw(const float* __restrict__ leg, const float* __restrict__ wq){
    size_t i = (size_t)blockIdx.x*256 + threadIdx.x;
    if (i >= LW_SZ) return;
    split2(leg[i]*wq[i & (NLAT_-1)], g_lw_h, g_lw_l, i);
}

// leg (l,m,j) -> lgt (m,j,l), tiled transpose over (l,j) at fixed m
__global__ void p_legT(const float* __restrict__ leg){
    __shared__ float sm[32][33];
    int m  = blockIdx.y;
    int tl = blockIdx.x & 7;
    int tj = blockIdx.x >> 3;
    int tx = threadIdx.x, ty = threadIdx.y;
    #pragma unroll
    for (int k=0;k<4;k++){
        int l = tl*32 + ty + k*8;
        sm[ty+k*8][tx] = leg[(size_t)l*M_*NLAT_ + (size_t)m*NLAT_ + tj*32 + tx];
    }
    __syncthreads();
    #pragma unroll
    for (int k=0;k<4;k++){
        int j = tj*32 + ty + k*8;
        int l = tl*32 + tx;
        size_t off = ((size_t)m*NLAT_ + j)*L_ + l;
        split2(sm[tx][ty+k*8], g_lg_h, g_lg_l, off);
    }
}

__global__ void p_W(const float* __restrict__ wr, const float* __restrict__ wi){
    size_t i = (size_t)blockIdx.x*256 + threadIdx.x;
    if (i >= (size_t)L_*C_*C_) return;
    int c = (int)(i & 255);
    int f = (int)((i>>8) & 255);
    int l = (int)(i>>16);
    float pos = (float)(l*(NREF_-1)) / (float)(L_-1);
    int i0 = (int)floorf(pos);
    if (i0 > NREF_-2) i0 = NREF_-2;
    float fr = pos - (float)i0;
    size_t base = ((size_t)f*C_ + c)*NREF_ + i0;
    float vre = wr[base]*(1.0f-fr) + wr[base+1]*fr;
    float vim = wi[base]*(1.0f-fr) + wi[base+1]*fr;
    size_t ob = ((size_t)l*C_ + f)*K2C_;
    split2( vre, g_wr_h, g_wr_l, ob + c);
    split2(-vim, g_wr_h, g_wr_l, ob + C_ + c);
    split2( vim, g_wi_h, g_wi_l, ob + c);
    split2( vre, g_wi_h, g_wi_l, ob + C_ + c);
}

__global__ void p_dft(){
    int i = blockIdx.x*256 + threadIdx.x;
    if (i < L_) g_lsc[i] = sqrtf(1.0f + (float)i) * (1.0f/(float)C_);
    if (i < (int)DCS_SZ){
        int n = i & 511;
        int m = (i >> 9) % M_;
        int ri = i / (M_*NLON_);
        int a = (m*n) & 511;
        float ang = (float)a * (1.0f/256.0f);
        float v = ri ? -sinpif(ang) : cospif(ang);
        split2(v, g_dc_h, g_dc_l, (size_t)i);
    }
    if (i < (int)D2_SZ){
        int mp = i % MP_;
        int n  = i / MP_;
        float v = 0.f;
        if (mp < M_){
            float wm = (mp==0 || mp==M_-1) ? 1.0f : 2.0f;
            int a = (mp*n) & 511;
            v = wm * cospif((float)a*(1.0f/256.0f)) * (1.0f/NLON_);
        } else if (mp < 2*M_-1+1){ // 257..513
            int m2 = mp - M_;
            if (m2 < M_){
                float wm = (m2==0 || m2==M_-1) ? 1.0f : 2.0f;
                int a = (m2*n) & 511;
                v = -wm * sinpif((float)a*(1.0f/256.0f)) * (1.0f/NLON_);
            }
        }
        split2(v, g_d2_h, g_d2_l, (size_t)i);
    }
}

__global__ void p_wT(const float* w1, const float* w2, const float* w3, const float* w4){
    int i = blockIdx.x*256 + threadIdx.x;
    if (i >= C_*C_) return;
    int c = i / C_, cp = i % C_;   // read w[c][cp], write wT[cp][c]
    const float* ws[4] = {w1, w2, w3, w4};
    #pragma unroll
    for (int k=0;k<4;k++){
        split2(ws[k][i], g_wt_h, g_wt_l, (size_t)k*C_*C_ + (size_t)cp*C_ + c);
    }
}

__global__ void p_zeroG2(){
    int i = blockIdx.x*256 + threadIdx.x;
    int tot = NLAT_*C_*(MP_ - 514);
    if (i >= tot) return;
    int k  = i % (MP_-514);
    int jf = i / (MP_-514);
    size_t off = (size_t)jf*MP_ + 514 + k;
    g_G_h[off] = __float2bfloat16(0.f);
    g_G_l[off] = __float2bfloat16(0.f);
}

// ---------------- split-bf16 tensor-core GEMM ----------------
// D[b,i,j] = scale(b) * sum_k (Ah+Al)[b,i,k]*(Bh+Bl)[b,j,k]  (3-term emulation)
//            (+biasJ[j]) -> ACT -> (+addsrc[off]); writes fp32 Dout and/or split (Oh,Ol)
#define MMA_OP(cc, aa, bb) asm volatile( \
    "mma.sync.aligned.m16n8k16.row.col.f32.bf16.bf16.f32 " \
    "{%0,%1,%2,%3},{%4,%5,%6,%7},{%8,%9},{%0,%1,%2,%3};" \
    : "+f"(cc[0]),"+f"(cc[1]),"+f"(cc[2]),"+f"(cc[3]) \
    : "r"(aa[0]),"r"(aa[1]),"r"(aa[2]),"r"(aa[3]),"r"(bb[0]),"r"(bb[1]))

template<int ACT>
__global__ __launch_bounds__(256) void mmagemm(
    const __nv_bfloat16* __restrict__ Ah, const __nv_bfloat16* __restrict__ Al,
    const __nv_bfloat16* __restrict__ Bh, const __nv_bfloat16* __restrict__ Bl,
    float* __restrict__ Dout,
    __nv_bfloat16* __restrict__ Oh, __nv_bfloat16* __restrict__ Ol,
    const float* __restrict__ biasJ, const float* __restrict__ bscale,
    const float* __restrict__ addsrc,
    int Mrows, int Ncols, int K,
    long sAi, long sAb, long sBi, long sBb,
    long sCi, long sCj, long sCb)
{
    __shared__ uint4 sAh[256], sAl[256], sBh[256], sBl[256];

    const int t    = threadIdx.x;
    const int lane = t & 31;
    const int warp = t >> 5;
    const int g    = lane >> 2;
    const int tig  = lane & 3;
    const int sw   = (lane >> 4) & 1;
    const int wm   = warp >> 2;     // 0..1
    const int wn   = warp & 3;      // 0..3
    const int bz   = blockIdx.z;
    const long i0  = (long)blockIdx.y * 128;
    const long j0  = (long)blockIdx.x * 128;

    const __nv_bfloat16* Ahb = Ah + (long)bz*sAb;
    const __nv_bfloat16* Alb = Al + (long)bz*sAb;
    const __nv_bfloat16* Bhb = Bh + (long)bz*sBb;
    const __nv_bfloat16* Blb = Bl + (long)bz*sBb;

    const int lr = t >> 1;            // 0..127 tile row
    const int kc = (t & 1) * 8;       // k sub-chunk
    const long arow = i0 + lr;
    const long brow = j0 + lr;
    const bool aok = arow < (long)Mrows;
    const bool bok = brow < (long)Ncols;
    const int pc = lr*2 + ((t&1) ^ ((lr>>2)&1));   // swizzled 16B-chunk index

    float acc[64];
    #pragma unroll
    for (int i=0;i<64;i++) acc[i] = 0.f;

    const uint4 z4 = make_uint4(0u,0u,0u,0u);
    uint4 rAh, rAl, rBh, rBl;
    {
        long ao = arow*sAi + kc, bo = brow*sBi + kc;
        rAh = aok ? *(const uint4*)(Ahb + ao) : z4;
        rAl = aok ? *(const uint4*)(Alb + ao) : z4;
        rBh = bok ? *(const uint4*)(Bhb + bo) : z4;
        rBl = bok ? *(const uint4*)(Blb + bo) : z4;
    }

    const int nk = K >> 4;
    const unsigned* A32h = (const unsigned*)sAh;
    const unsigned* A32l = (const unsigned*)sAl;
    const unsigned* B32h = (const unsigned*)sBh;
    const unsigned* B32l = (const unsigned*)sBl;

    for (int ks = 0; ks < nk; ks++){
        __syncthreads();
        sAh[pc] = rAh; sAl[pc] = rAl; sBh[pc] = rBh; sBl[pc] = rBl;
        __syncthreads();
        if (ks + 1 < nk){
            long kq = (long)(ks+1)*16 + kc;
            long ao = arow*sAi + kq, bo = brow*sBi + kq;
            rAh = aok ? *(const uint4*)(Ahb + ao) : z4;
            rAl = aok ? *(const uint4*)(Alb + ao) : z4;
            rBh = bok ? *(const uint4*)(Bhb + bo) : z4;
            rBl = bok ? *(const uint4*)(Blb + bo) : z4;
        }
        // fragments
        unsigned bh[4][2], bl[4][2], ah[4][4], al[4][4];
        #pragma unroll
        for (int nt=0; nt<4; nt++){
            int base = (wn*32 + nt*8 + g)*8 + tig;
            bh[nt][0] = B32h[base + sw*4];
            bh[nt][1] = B32h[base + (sw^1)*4];
            bl[nt][0] = B32l[base + sw*4];
            bl[nt][1] = B32l[base + (sw^1)*4];
        }
        #pragma unroll
        for (int mt=0; mt<4; mt++){
            int r0 = wm*64 + mt*16 + g;
            int b0 = r0*8 + tig;
            int b1 = (r0+8)*8 + tig;
            ah[mt][0] = A32h[b0 + sw*4];
            ah[mt][1] = A32h[b1 + sw*4];
            ah[mt][2] = A32h[b0 + (sw^1)*4];
            ah[mt][3] = A32h[b1 + (sw^1)*4];
            al[mt][0] = A32l[b0 + sw*4];
            al[mt][1] = A32l[b1 + sw*4];
            al[mt][2] = A32l[b0 + (sw^1)*4];
            al[mt][3] = A32l[b1 + (sw^1)*4];
        }
        #pragma unroll
        for (int mt=0; mt<4; mt++)
            #pragma unroll
            for (int nt=0; nt<4; nt++) MMA_OP((&acc[(mt*4+nt)*4]), ah[mt], bh[nt]);
        #pragma unroll
        for (int mt=0; mt<4; mt++)
            #pragma unroll
            for (int nt=0; nt<4; nt++) MMA_OP((&acc[(mt*4+nt)*4]), ah[mt], bl[nt]);
        #pragma unroll
        for (int mt=0; mt<4; mt++)
            #pragma unroll
            for (int nt=0; nt<4; nt++) MMA_OP((&acc[(mt*4+nt)*4]), al[mt], bh[nt]);
    }

    float scl = bscale ? bscale[bz] : 1.0f;
    #pragma unroll
    for (int mt=0; mt<4; mt++){
        long rA = i0 + wm*64 + mt*16 + g;
        #pragma unroll
        for (int nt=0; nt<4; nt++){
            long cB = j0 + wn*32 + nt*8 + 2*tig;
            float* a = &acc[(mt*4+nt)*4];
            #pragma unroll
            for (int h=0; h<2; h++){
                long row = rA + h*8;
                if (row >= (long)Mrows) continue;
                #pragma unroll
                for (int q=0; q<2; q++){
                    long col = cB + q;
                    if (col >= (long)Ncols) continue;
                    float v = a[h*2+q] * scl;
                    if (biasJ) v += biasJ[col];
                    if (ACT == 1) v = gelu_f(v);
                    long off = (long)bz*sCb + row*sCi + col*sCj;
                    if (addsrc) v += addsrc[off];
                    if (Dout) Dout[off] = v;
                    if (Oh) split2(v, Oh, Ol, (size_t)off);
                }
            }
        }
    }
}

// ---------------- norm + finalize ----------------
__global__ void norm1_k(){
    int b = blockIdx.x, c = threadIdx.x;
    const float* base = g_grids + (size_t)b*256*C_;
    float s=0.f, q=0.f;
    for (int r=0;r<256;r++){
        float v = base[(size_t)r*C_ + c];
        s += v; q = fmaf(v,v,q);
    }
    g_part[0][b][c] = s;
    g_part[1][b][c] = q;
}
__global__ void norm2_k(){
    int c = threadIdx.x;
    float s=0.f, q=0.f;
    for (int b=0;b<512;b++){ s += g_part[0][b][c]; q += g_part[1][b][c]; }
    float mu = s * (1.0f/(float)S_);
    float var = q * (1.0f/(float)S_) - mu*mu;
    g_mu[c] = mu;
    g_rstd[c] = rsqrtf(var + 1e-3f);
}
// y2 (s,c) -> out (c,j,n) with norm + residual
__global__ void fin_k(const float* __restrict__ x,
                      const float* __restrict__ gamma,
                      const float* __restrict__ beta,
                      float* __restrict__ out){
    __shared__ float sm[32][33];
    int j  = blockIdx.y;
    int tc = blockIdx.x & 7;
    int tn = blockIdx.x >> 3;
    int tx = threadIdx.x, ty = threadIdx.y;
    #pragma unroll
    for (int k=0;k<4;k++){
        int n = tn*32 + ty + k*8;
        sm[ty+k*8][tx] = g_grids[((size_t)n*NLAT_ + j)*C_ + tc*32 + tx];
    }
    __syncthreads();
    #pragma unroll
    for (int k=0;k<4;k++){
        int c = tc*32 + ty + k*8;
        int n = tn*32 + tx;
        size_t off = (size_t)c*S_ + (size_t)j*NLON_ + n;
        float v = sm[tx][ty+k*8];
        out[off] = (v - g_mu[c])*g_rstd[c]*gamma[c] + beta[c] + x[off];
    }
}

// ---------------- host side ----------------
#define DEVPTR(T, var, sym) T* var; cudaGetSymbolAddress((void**)&var, sym)

static void launch_gemm(int act, dim3 grid,
    const __nv_bfloat16* Ah, const __nv_bfloat16* Al,
    const __nv_bfloat16* Bh, const __nv_bfloat16* Bl,
    float* Dout, __nv_bfloat16* Oh, __nv_bfloat16* Ol,
    const float* biasJ, const float* bscale, const float* addsrc,
    int M, int N, int K,
    long sAi, long sAb, long sBi, long sBb, long sCi, long sCj, long sCb)
{
    if (act)
        mmagemm<1><<<grid,256>>>(Ah,Al,Bh,Bl,Dout,Oh,Ol,biasJ,bscale,addsrc,
                                 M,N,K,sAi,sAb,sBi,sBb,sCi,sCj,sCb);
    else
        mmagemm<0><<<grid,256>>>(Ah,Al,Bh,Bl,Dout,Oh,Ol,biasJ,bscale,addsrc,
                                 M,N,K,sAi,sAb,sBi,sBb,sCi,sCj,sCb);
}

extern "C" void kernel_launch(void* const* d_in, const int* in_sizes, int n_in,
                              void* d_out, int out_size){
    const float* x      = (const float*)d_in[0];
    const float* leg    = (const float*)d_in[1];
    const float* wquad  = (const float*)d_in[2];
    const float* w_real = (const float*)d_in[3];
    const float* w_imag = (const float*)d_in[4];
    const float* m1w1   = (const float*)d_in[5];
    const float* m1b1   = (const float*)d_in[6];
    const float* m1w2   = (const float*)d_in[7];
    const float* m1b2   = (const float*)d_in[8];
    const float* m2w1   = (const float*)d_in[9];
    const float* m2b1   = (const float*)d_in[10];
    const float* m2w2   = (const float*)d_in[11];
    const float* m2b2   = (const float*)d_in[12];
    const float* gamma  = (const float*)d_in[13];
    const float* beta   = (const float*)d_in[14];
    float* out = (float*)d_out;

    DEVPTR(__nv_bfloat16, xh, g_x_h);  DEVPTR(__nv_bfloat16, xl, g_x_l);
    DEVPTR(__nv_bfloat16, xth,g_xt_h); DEVPTR(__nv_bfloat16, xtl,g_xt_l);
    DEVPTR(__nv_bfloat16, lwh,g_lw_h); DEVPTR(__nv_bfloat16, lwl,g_lw_l);
    DEVPTR(__nv_bfloat16, lgh,g_lg_h); DEVPTR(__nv_bfloat16, lgl,g_lg_l);
    DEVPTR(__nv_bfloat16, wrh,g_wr_h); DEVPTR(__nv_bfloat16, wrl,g_wr_l);
    DEVPTR(__nv_bfloat16, wih,g_wi_h); DEVPTR(__nv_bfloat16, wil,g_wi_l);
    DEVPTR(__nv_bfloat16, Fh, g_F_h);  DEVPTR(__nv_bfloat16, Fl, g_F_l);
    DEVPTR(__nv_bfloat16, Hh, g_H_h);  DEVPTR(__nv_bfloat16, Hl, g_H_l);
    DEVPTR(__nv_bfloat16, xrh,g_xr_h); DEVPTR(__nv_bfloat16, xrl,g_xr_l);
    DEVPTR(__nv_bfloat16, xih,g_xi_h); DEVPTR(__nv_bfloat16, xil,g_xi_l);
    DEVPTR(__nv_bfloat16, Gh, g_G_h);  DEVPTR(__nv_bfloat16, Gl, g_G_l);
    DEVPTR(__nv_bfloat16, mAh,g_mA_h); DEVPTR(__nv_bfloat16, mAl,g_mA_l);
    DEVPTR(__nv_bfloat16, mBh,g_mB_h); DEVPTR(__nv_bfloat16, mBl,g_mB_l);
    DEVPTR(__nv_bfloat16, dch,g_dc_h); DEVPTR(__nv_bfloat16, dcl,g_dc_l);
    DEVPTR(__nv_bfloat16, d2h,g_d2_h); DEVPTR(__nv_bfloat16, d2l,g_d2_l);
    DEVPTR(__nv_bfloat16, wth,g_wt_h); DEVPTR(__nv_bfloat16, wtl,g_wt_l);
    DEVPTR(float, grids, g_grids);
    DEVPTR(float, lsc,   g_lsc);

    // ---- prep ----
    p_split_x<<<(unsigned)((XS_SZ+255)/256), 256>>>(x);
    p_xT     <<<dim3(128, NLAT_), dim3(32,8)>>>(x);
    p_lw     <<<(unsigned)((LW_SZ+255)/256), 256>>>(leg, wquad);
    p_legT   <<<dim3(64, M_), dim3(32,8)>>>(leg);
    p_W      <<<(unsigned)(((size_t)L_*C_*C_+255)/256), 256>>>(w_real, w_imag);
    p_dft    <<<(D2_SZ+255)/256, 256>>>();
    p_wT     <<<(C_*C_+255)/256, 256>>>(m1w1, m1w2, m2w1, m2w2);
    p_zeroG2 <<<(NLAT_*C_*14+255)/256, 256>>>();

    // ---- S1: rfft. D[cj, m] batched over ri; out F (ri,m,c,j) split ----
    launch_gemm(0, dim3(3, 512, 2),
        xh, xl, dch, dcl, nullptr, Fh, Fl, nullptr, nullptr, nullptr,
        C_*NLAT_, M_, NLON_,
        NLON_, 0, NLON_, (long)M_*NLON_,
        1, (long)C_*NLAT_, (long)M_*C_*NLAT_);

    // ---- S2: Legendre fwd (batch m): D[l, c] -> H (l,m,2C) ----
    launch_gemm(0, dim3(2, 2, M_),
        lwh, lwl, Fh, Fl, nullptr, Hh, Hl, nullptr, nullptr, nullptr,
        L_, C_, NLAT_,
        (long)M_*NLAT_, NLAT_, NLAT_, (long)C_*NLAT_,
        (long)M_*K2C_, 1, K2C_);
    launch_gemm(0, dim3(2, 2, M_),
        lwh, lwl, Fh + M_*(size_t)C_*NLAT_, Fl + M_*(size_t)C_*NLAT_,
        nullptr, Hh + C_, Hl + C_, nullptr, nullptr, nullptr,
        L_, C_, NLAT_,
        (long)M_*NLAT_, NLAT_, NLAT_, (long)C_*NLAT_,
        (long)M_*K2C_, 1, K2C_);

    // ---- S3: spectral conv (batch l): D[f, m] -> xs (m,f,l) split, scale lsc ----
    launch_gemm(0, dim3(3, 2, L_),
        wrh, wrl, Hh, Hl, nullptr, xrh, xrl, nullptr, lsc, nullptr,
        C_, M_, K2C_,
        K2C_, (long)C_*K2C_, K2C_, (long)M_*K2C_,
        L_, (long)C_*L_, 1);
    launch_gemm(0, dim3(3, 2, L_),
        wih, wil, Hh, Hl, nullptr, xih, xil, nullptr, lsc, nullptr,
        C_, M_, K2C_,
        K2C_, (long)C_*K2C_, K2C_, (long)M_*K2C_,
        L_, (long)C_*L_, 1);

    // ---- S4: Legendre inv (batch m): D[j, f] -> G2 (j,f,528) split ----
    launch_gemm(0, dim3(2, 2, M_),
        lgh, lgl, xrh, xrl, nullptr, Gh, Gl, nullptr, nullptr, nullptr,
        NLAT_, C_, L_,
        L_, (long)NLAT_*L_, L_, (long)C_*L_,
        (long)C_*MP_, MP_, 1);
    launch_gemm(0, dim3(2, 2, M_),
        lgh, lgl, xih, xil, nullptr, Gh + M_, Gl + M_, nullptr, nullptr, nullptr,
        NLAT_, C_, L_,
        L_, (long)NLAT_*L_, L_, (long)C_*L_,
        (long)C_*MP_, MP_, 1);

    // ---- S5: irfft + GELU. D[n, jf] -> grids (n,j,f) fp32 ----
    launch_gemm(1, dim3(512, 4, 1),
        d2h, d2l, Gh, Gl, grids, nullptr, nullptr, nullptr, nullptr, nullptr,
        NLON_, NLAT_*C_, MP_,
        MP_, 0, MP_, 0,
        (long)NLAT_*C_, 1, 0);

    // ---- MLP1: h1 = gelu(xT @ w1 + b1) -> mA split (s,c) ----
    launch_gemm(1, dim3(2, 1024, 1),
        xth, xtl, wth + 0, wtl + 0, nullptr, mAh, mAl, m1b1, nullptr, nullptr,
        S_, C_, C_, C_, 0, C_, 0, C_, 1, 0);
    // ---- MLP2: y1 = gelu(h1 @ w2 + b2) + grids -> mB split ----
    launch_gemm(1, dim3(2, 1024, 1),
        mAh, mAl, wth + C_*C_, wtl + C_*C_, nullptr, mBh, mBl, m1b2, nullptr, grids,
        S_, C_, C_, C_, 0, C_, 0, C_, 1, 0);
    // ---- MLP3 ----
    launch_gemm(1, dim3(2, 1024, 1),
        mBh, mBl, wth + 2*C_*C_, wtl + 2*C_*C_, nullptr, mAh, mAl, m2b1, nullptr, nullptr,
        S_, C_, C_, C_, 0, C_, 0, C_, 1, 0);
    // ---- MLP4: y2 -> grids (fp32) ----
    launch_gemm(1, dim3(2, 1024, 1),
        mAh, mAl, wth + 3*C_*C_, wtl + 3*C_*C_, grids, nullptr, nullptr, m2b2, nullptr, nullptr,
        S_, C_, C_, C_, 0, C_, 0, C_, 1, 0);

    // ---- instance norm + residual + transpose out ----
    norm1_k<<<512, 256>>>();
    norm2_k<<<1, 256>>>();
    fin_k<<<dim3(128, NLAT_), dim3(32,8)>>>(x, gamma, beta, out);
}